// round 8
// baseline (speedup 1.0000x reference)
#include <cuda_runtime.h>
#include <cuda_fp16.h>
#include <math.h>
#include <stdint.h>

#define BATCH 16
#define CHN   640
#define SP    4096
#define TT    77
#define XDIM  768
#define NHE   8
#define HDIM  80
#define INNER 640

// ---------------- scratch ----------------
__device__ __half g_q16 [(size_t)BATCH * SP * INNER];
__device__ __half g_k16 [(size_t)BATCH * TT * INNER];
__device__ __half g_v16 [(size_t)BATCH * TT * INNER];
__device__ __half g_x16 [(size_t)BATCH * SP * CHN];
__device__ __half g_at16[(size_t)BATCH * SP * INNER];
__device__ __half g_e16 [(size_t)BATCH * TT * XDIM];
__device__ __half g_wq16[(size_t)INNER * CHN];
__device__ __half g_wk16[(size_t)INNER * XDIM];
__device__ __half g_wv16[(size_t)INNER * XDIM];
__device__ __half g_wo16[(size_t)CHN * INNER];
__device__ float  g_mu  [(size_t)BATCH * SP];
__device__ float  g_rs  [(size_t)BATCH * SP];

// ---------------- helpers ----------------
__device__ __forceinline__ uint32_t smem_u32(const void* p) {
    uint32_t a;
    asm("{ .reg .u64 t; cvta.to.shared.u64 t, %1; cvt.u32.u64 %0, t; }"
        : "=r"(a) : "l"(p));
    return a;
}
__device__ __forceinline__ void cp16(uint32_t dst, const void* src, bool v) {
    int sz = v ? 16 : 0;
    asm volatile("cp.async.cg.shared.global [%0], [%1], 16, %2;"
                 :: "r"(dst), "l"(src), "r"(sz) : "memory");
}
#define CP_COMMIT() asm volatile("cp.async.commit_group;" ::: "memory")
#define CP_WAIT1()  asm volatile("cp.async.wait_group 1;" ::: "memory")
#define CP_WAIT0()  asm volatile("cp.async.wait_group 0;" ::: "memory")

__device__ __forceinline__ void mma_f16(float c[4], unsigned a0, unsigned a1,
                                        unsigned a2, unsigned a3,
                                        unsigned b0, unsigned b1)
{
    asm volatile(
        "mma.sync.aligned.m16n8k16.row.col.f32.f16.f16.f32 "
        "{%0,%1,%2,%3},{%4,%5,%6,%7},{%8,%9},{%0,%1,%2,%3};"
        : "+f"(c[0]), "+f"(c[1]), "+f"(c[2]), "+f"(c[3])
        : "r"(a0), "r"(a1), "r"(a2), "r"(a3), "r"(b0), "r"(b1));
}

// ---------------- LN stats ----------------
__global__ void __launch_bounds__(256) ln_stats(const float* __restrict__ x)
{
    int s = blockIdx.x * 256 + threadIdx.x;
    int b = blockIdx.y;
    const float* xp = x + (size_t)b * CHN * SP + s;
    float sum = 0.f, sumsq = 0.f;
    for (int c = 0; c < CHN; c++) { float v = xp[(size_t)c * SP]; sum += v; sumsq += v * v; }
    float mu = sum * (1.0f / CHN);
    float var = sumsq * (1.0f / CHN) - mu * mu;
    g_mu[(size_t)b * SP + s] = mu;
    g_rs[(size_t)b * SP + s] = rsqrtf(var + 1e-6f);
}

// ---------------- normalize + transpose -> fp16 [b][s][c] ----------------
__global__ void __launch_bounds__(256) ln_t16(const float* __restrict__ x,
                                              const float* __restrict__ lw,
                                              const float* __restrict__ lb)
{
    __shared__ float t[32][33];
    int s0 = blockIdx.x * 32, c0 = blockIdx.y * 32, b = blockIdx.z;
    int xl = threadIdx.x & 31, y = (threadIdx.x >> 5) * 4;
#pragma unroll
    for (int i = 0; i < 4; i++)
        t[y + i][xl] = x[((size_t)b * CHN + c0 + y + i) * SP + s0 + xl];
    __syncthreads();
    float wv = lw[c0 + xl], bv = lb[c0 + xl];
#pragma unroll
    for (int i = 0; i < 4; i++) {
        int s = s0 + y + i;
        float mu = g_mu[(size_t)b * SP + s];
        float rs = g_rs[(size_t)b * SP + s];
        float v = (t[xl][y + i] - mu) * rs * wv + bv;
        g_x16[((size_t)b * SP + s) * CHN + c0 + xl] = __float2half_rn(v);
    }
}

// ---------------- weight transpose+cvt [R][C] fp32 -> [C][R] fp16 ----------------
__global__ void __launch_bounds__(256) cvt_w_t(const float* __restrict__ in,
                                               __half* __restrict__ out, int R, int C)
{
    __shared__ float t[32][33];
    int c0 = blockIdx.x * 32, r0 = blockIdx.y * 32;
    int xl = threadIdx.x & 31, y = (threadIdx.x >> 5) * 4;
#pragma unroll
    for (int i = 0; i < 4; i++)
        t[y + i][xl] = in[(size_t)(r0 + y + i) * C + c0 + xl];
    __syncthreads();
#pragma unroll
    for (int i = 0; i < 4; i++)
        out[(size_t)(c0 + y + i) * R + r0 + xl] = __float2half_rn(t[xl][y + i]);
}

// ---------------- elementwise cvt ----------------
__global__ void __launch_bounds__(256) cvt16(const float* __restrict__ in,
                                             __half* __restrict__ out, int n)
{
    int i = blockIdx.x * 256 + threadIdx.x;
    if (i < n) out[i] = __float2half_rn(in[i]);
}

// ---------------- fp16 mma GEMM: D = A[M][K] * Bt[N][K]^T ----------------
// EPI 0: C[m][n] fp32;  EPI 1: out[b][n][s] fp32 + bias + resid;  EPI 2: C[m][n] fp16
#define HBOFF  10240
#define HSTG   20480
#define HGSMEM (3 * HSTG)

template<int EPI, bool MG>
__global__ void __launch_bounds__(256, 2)
gemm_h(const __half* __restrict__ A, const __half* __restrict__ Bt,
       void* __restrict__ CoutV, int M, int N, int K, int lda,
       const float* __restrict__ bias, const float* __restrict__ resid)
{
    extern __shared__ char smc[];
    uint32_t sb = smem_u32(smc);

    int tid = threadIdx.x, lane = tid & 31, w = tid >> 5;
    int r = lane >> 2, q = lane & 3;
    int wm = w & 3, wn = w >> 2;
    int m0 = blockIdx.y * 128;
    int n0 = blockIdx.x * 128;
    int mb = wm * 32, nb = wn * 64;
    int NT = K >> 5;

    float acc[2][8][4];
#pragma unroll
    for (int i = 0; i < 2; i++)
#pragma unroll
        for (int j = 0; j < 8; j++)
#pragma unroll
            for (int l = 0; l < 4; l++) acc[i][j][l] = 0.f;

    auto load_stage = [&](int slot, int k0) {
        uint32_t st = sb + slot * HSTG;
#pragma unroll
        for (int i = 0; i < 2; i++) {
            int cid = tid + i * 256;
            int row = cid >> 2, ch = cid & 3;
            bool v = !MG || (m0 + row) < M;
            cp16(st + row * 80 + ch * 16,
                 A + (size_t)(m0 + row) * lda + k0 + ch * 8, v);
        }
#pragma unroll
        for (int i = 0; i < 2; i++) {
            int cid = tid + i * 256;
            int row = cid >> 2, ch = cid & 3;
            cp16(st + HBOFF + row * 80 + ch * 16,
                 Bt + (size_t)(n0 + row) * K + k0 + ch * 8, true);
        }
    };

    auto lda_frag = [&](unsigned af[2][4], const __half* As, int kb) {
        int kof = kb + 2 * q;
#pragma unroll
        for (int im = 0; im < 2; im++) {
            int mrow = mb + im * 16 + r;
            af[im][0] = *(const unsigned*)&As[mrow * 40 + kof];
            af[im][1] = *(const unsigned*)&As[(mrow + 8) * 40 + kof];
            af[im][2] = *(const unsigned*)&As[mrow * 40 + kof + 8];
            af[im][3] = *(const unsigned*)&As[(mrow + 8) * 40 + kof + 8];
        }
    };

    load_stage(0, 0);  CP_COMMIT();
    load_stage(1, 32); CP_COMMIT();

    for (int t = 0; t < NT; t++) {
        if (t == NT - 1) CP_WAIT0(); else CP_WAIT1();
        __syncthreads();
        if (t + 2 < NT) { load_stage((t + 2) % 3, (t + 2) * 32); CP_COMMIT(); }

        int slot = t % 3;
        const __half* As = (const __half*)(smc + slot * HSTG);
        const __half* Bs = (const __half*)(smc + slot * HSTG + HBOFF);

        unsigned ac[2][4], an[2][4];
        lda_frag(ac, As, 0);
#pragma unroll
        for (int kc = 0; kc < 2; kc++) {
            if (kc == 0) lda_frag(an, As, 16);
            int kof = kc * 16 + 2 * q;
#pragma unroll
            for (int half_ = 0; half_ < 2; half_++) {
                unsigned bb[4][2];
#pragma unroll
                for (int i = 0; i < 4; i++) {
                    int ncol = nb + (half_ * 4 + i) * 8 + r;
                    bb[i][0] = *(const unsigned*)&Bs[ncol * 40 + kof];
                    bb[i][1] = *(const unsigned*)&Bs[ncol * 40 + kof + 8];
                }
#pragma unroll
                for (int i = 0; i < 4; i++) {
                    int in_ = half_ * 4 + i;
#pragma unroll
                    for (int im = 0; im < 2; im++)
                        mma_f16(acc[im][in_], ac[im][0], ac[im][1], ac[im][2],
                                ac[im][3], bb[i][0], bb[i][1]);
                }
            }
            if (kc == 0) {
#pragma unroll
                for (int im = 0; im < 2; im++)
#pragma unroll
                    for (int j = 0; j < 4; j++) ac[im][j] = an[im][j];
            }
        }
    }
    __syncthreads();

    // -------- epilogue --------
    float* Cs = (float*)smc;
    if (EPI != 1) {
#pragma unroll 1
        for (int ch = 0; ch < 4; ch++) {
            __syncthreads();
            if (wm == ch) {
#pragma unroll
                for (int im = 0; im < 2; im++) {
                    int r0 = im * 16 + r;
#pragma unroll
                    for (int in_ = 0; in_ < 8; in_++) {
                        int cc = nb + in_ * 8 + q * 2;
                        Cs[r0 * 132 + cc]           = acc[im][in_][0];
                        Cs[r0 * 132 + cc + 1]       = acc[im][in_][1];
                        Cs[(r0 + 8) * 132 + cc]     = acc[im][in_][2];
                        Cs[(r0 + 8) * 132 + cc + 1] = acc[im][in_][3];
                    }
                }
            }
            __syncthreads();
            for (int t = tid; t < 32 * 128; t += 256) {
                int ml = t >> 7, n = t & 127;
                int m = m0 + ch * 32 + ml;
                if (MG && m >= M) continue;
                if (EPI == 0)
                    ((float*)CoutV)[(size_t)m * N + n0 + n] = Cs[ml * 132 + n];
                else
                    ((__half*)CoutV)[(size_t)m * N + n0 + n] =
                        __float2half_rn(Cs[ml * 132 + n]);
            }
        }
    } else {
#pragma unroll 1
        for (int ch = 0; ch < 4; ch++) {
            __syncthreads();
            if (wn == (ch >> 1)) {
                int inlo = (ch & 1) * 4;
#pragma unroll
                for (int im = 0; im < 2; im++) {
                    int mrow = mb + im * 16 + r;
#pragma unroll
                    for (int ii = 0; ii < 4; ii++) {
                        int in_ = inlo + ii;
                        int nl = in_ * 8 + q * 2 - (ch & 1) * 32;
                        Cs[nl * 132 + mrow]           = acc[im][in_][0];
                        Cs[(nl + 1) * 132 + mrow]     = acc[im][in_][1];
                        Cs[nl * 132 + mrow + 8]       = acc[im][in_][2];
                        Cs[(nl + 1) * 132 + mrow + 8] = acc[im][in_][3];
                    }
                }
            }
            __syncthreads();
            for (int t = tid; t < 32 * 128; t += 256) {
                int nl = t >> 7, ml = t & 127;
                int n = n0 + ch * 32 + nl;
                int m = m0 + ml;
                int b = m >> 12, s = m & (SP - 1);
                size_t addr = (size_t)b * CHN * SP + (size_t)n * SP + s;
                ((float*)CoutV)[addr] = Cs[nl * 132 + ml] + bias[n] + resid[addr];
            }
        }
    }
}

// ---------------- fp16 tensor-core attention ----------------
// Ks[80][88] (t,d) + Vt[80][88] (d,t) fp16 = 28160B smem.
// S C-fragment layout == PV A-fragment layout -> no P transpose at all.
#define AT_SMEM 28160

__global__ void __launch_bounds__(256, 2) attn_mma()
{
    extern __shared__ __half smh[];
    __half* Ks = smh;            // [80][88]  row=t, col=d
    __half* Vt = smh + 7040;     // [80][88]  row=d, col=t

    int tid = threadIdx.x, lane = tid & 31, w = tid >> 5;
    int b = blockIdx.z, h = blockIdx.y;
    int q0 = blockIdx.x * 128;
    int mb = w * 16;
    int r = lane >> 2, q = lane & 3, q2 = q * 2;
    uint32_t sb = smem_u32(smh);

    const __half* kg = g_k16 + (size_t)b * TT * INNER + h * HDIM;
    const __half* vg = g_v16 + (size_t)b * TT * INNER + h * HDIM;

    // K: 77 rows x 10 16B-chunks via cp.async
#pragma unroll
    for (int i = 0; i < 4; i++) {
        int cid = tid + i * 256;
        if (cid < 770) {
            int t = cid / 10, ch = cid % 10;
            cp16(sb + (t * 88 + ch * 8) * 2, kg + (size_t)t * INNER + ch * 8, true);
        }
    }
    CP_COMMIT();

    // Q fragments (fp16 direct from gmem)
    const __half* qg = g_q16 + ((size_t)b * SP + q0 + mb) * INNER + h * HDIM;
    unsigned qf[5][4];
#pragma unroll
    for (int k8 = 0; k8 < 5; k8++) {
        int c = k8 * 16 + q2;
        qf[k8][0] = *(const unsigned*)&qg[(size_t)r * INNER + c];
        qf[k8][1] = *(const unsigned*)&qg[(size_t)(r + 8) * INNER + c];
        qf[k8][2] = *(const unsigned*)&qg[(size_t)r * INNER + c + 8];
        qf[k8][3] = *(const unsigned*)&qg[(size_t)(r + 8) * INNER + c + 8];
    }

    // V transposed staging: [t][d] -> Vt[d][t]
#pragma unroll
    for (int i = 0; i < 13; i++) {
        int cid = tid + i * 256;
        if (cid < 3080) {
            int t = cid / 40, d2 = cid % 40;
            __half2 v = *(const __half2*)&vg[(size_t)t * INNER + 2 * d2];
            Vt[(2 * d2) * 88 + t]     = __low2half(v);
            Vt[(2 * d2 + 1) * 88 + t] = __high2half(v);
        }
    }
    if (tid < 240) {                  // zero pads (t = 77..79)
        int rr = 77 + tid / 80, cc = tid % 80;
        Ks[rr * 88 + cc] = __float2half(0.f);
        Vt[cc * 88 + rr] = __float2half(0.f);
    }
    CP_WAIT0();
    __syncthreads();

    // ---- S = Q K^T ----
    float acc[10][4];
#pragma unroll
    for (int i = 0; i < 10; i++)
#pragma unroll
        for (int j = 0; j < 4; j++) acc[i][j] = 0.f;

#pragma unroll
    for (int k8 = 0; k8 < 5; k8++) {
        int kof = k8 * 16 + q2;
#pragma unroll
        for (int in_ = 0; in_ < 10; in_++) {
            int t = in_ * 8 + r;
            unsigned b0 = *(const unsigned*)&Ks[t * 88 + kof];
            unsigned b1 = *(const unsigned*)&Ks[t * 88 + kof + 8];
            mma_f16(acc[in_], qf[k8][0], qf[k8][1], qf[k8][2], qf[k8][3], b0, b1);
        }
    }

    // ---- softmax (un-normalized; keep 1/sum) ----
    const float scale = 0.11180339887498949f;
    float invs[2];
#pragma unroll
    for (int hf = 0; hf < 2; hf++) {
        float mx = -1e30f;
#pragma unroll
        for (int in_ = 0; in_ < 10; in_++) {
            int c0 = in_ * 8 + q2;
            float v0 = (c0     < TT) ? acc[in_][hf * 2]     * scale : -1e30f;
            float v1 = (c0 + 1 < TT) ? acc[in_][hf * 2 + 1] * scale : -1e30f;
            acc[in_][hf * 2] = v0; acc[in_][hf * 2 + 1] = v1;
            mx = fmaxf(mx, fmaxf(v0, v1));
        }
        mx = fmaxf(mx, __shfl_xor_sync(0xffffffffu, mx, 1));
        mx = fmaxf(mx, __shfl_xor_sync(0xffffffffu, mx, 2));
        float s = 0.f;
#pragma unroll
        for (int in_ = 0; in_ < 10; in_++) {
            int c0 = in_ * 8 + q2;
            float e0 = (c0     < TT) ? __expf(acc[in_][hf * 2]     - mx) : 0.f;
            float e1 = (c0 + 1 < TT) ? __expf(acc[in_][hf * 2 + 1] - mx) : 0.f;
            acc[in_][hf * 2] = e0; acc[in_][hf * 2 + 1] = e1;
            s += e0 + e1;
        }
        s += __shfl_xor_sync(0xffffffffu, s, 1);
        s += __shfl_xor_sync(0xffffffffu, s, 2);
        invs[hf] = 1.f / s;
    }

    // ---- P fragments: direct repack of S accumulators (no shuffles) ----
    unsigned pf[5][4];
#pragma unroll
    for (int k8 = 0; k8 < 5; k8++) {
        __half2 h0 = __floats2half2_rn(acc[2 * k8][0],     acc[2 * k8][1]);
        __half2 h1 = __floats2half2_rn(acc[2 * k8][2],     acc[2 * k8][3]);
        __half2 h2 = __floats2half2_rn(acc[2 * k8 + 1][0], acc[2 * k8 + 1][1]);
        __half2 h3 = __floats2half2_rn(acc[2 * k8 + 1][2], acc[2 * k8 + 1][3]);
        pf[k8][0] = *(unsigned*)&h0;
        pf[k8][1] = *(unsigned*)&h1;
        pf[k8][2] = *(unsigned*)&h2;
        pf[k8][3] = *(unsigned*)&h3;
    }

    // ---- O = P V ----
    float oc[10][4];
#pragma unroll
    for (int i = 0; i < 10; i++)
#pragma unroll
        for (int j = 0; j < 4; j++) oc[i][j] = 0.f;

#pragma unroll
    for (int k8 = 0; k8 < 5; k8++) {
        int kof = k8 * 16 + q2;
#pragma unroll
        for (int in_ = 0; in_ < 10; in_++) {
            int d = in_ * 8 + r;
            unsigned b0 = *(const unsigned*)&Vt[d * 88 + kof];
            unsigned b1 = *(const unsigned*)&Vt[d * 88 + kof + 8];
            mma_f16(oc[in_], pf[k8][0], pf[k8][1], pf[k8][2], pf[k8][3], b0, b1);
        }
    }

    // ---- normalize + write fp16 ----
    __half* og = g_at16 + ((size_t)b * SP + q0 + mb) * INNER + h * HDIM;
#pragma unroll
    for (int in_ = 0; in_ < 10; in_++) {
        int c = in_ * 8 + q2;
        *(__half2*)(og + (size_t)r * INNER + c) =
            __floats2half2_rn(oc[in_][0] * invs[0], oc[in_][1] * invs[0]);
        *(__half2*)(og + (size_t)(r + 8) * INNER + c) =
            __floats2half2_rn(oc[in_][2] * invs[1], oc[in_][3] * invs[1]);
    }
}

// ---------------- launch ----------------
extern "C" void kernel_launch(void* const* d_in, const int* in_sizes, int n_in,
                              void* d_out, int out_size)
{
    (void)in_sizes; (void)n_in; (void)out_size;
    const float* hs  = (const float*)d_in[0];
    const float* enc = (const float*)d_in[1];
    const float* lnw = (const float*)d_in[2];
    const float* lnb = (const float*)d_in[3];
    const float* wq  = (const float*)d_in[4];
    const float* wk  = (const float*)d_in[5];
    const float* wv  = (const float*)d_in[6];
    const float* wo  = (const float*)d_in[7];
    const float* bo  = (const float*)d_in[8];
    float* out = (float*)d_out;

    __half *p_q16, *p_k16, *p_v16, *p_x16, *p_at16, *p_e16;
    __half *p_wq16, *p_wk16, *p_wv16, *p_wo16;
    cudaGetSymbolAddress((void**)&p_q16,  g_q16);
    cudaGetSymbolAddress((void**)&p_k16,  g_k16);
    cudaGetSymbolAddress((void**)&p_v16,  g_v16);
    cudaGetSymbolAddress((void**)&p_x16,  g_x16);
    cudaGetSymbolAddress((void**)&p_at16, g_at16);
    cudaGetSymbolAddress((void**)&p_e16,  g_e16);
    cudaGetSymbolAddress((void**)&p_wq16, g_wq16);
    cudaGetSymbolAddress((void**)&p_wk16, g_wk16);
    cudaGetSymbolAddress((void**)&p_wv16, g_wv16);
    cudaGetSymbolAddress((void**)&p_wo16, g_wo16);

    cudaFuncSetAttribute(gemm_h<2, false>,
                         cudaFuncAttributeMaxDynamicSharedMemorySize, HGSMEM);
    cudaFuncSetAttribute(gemm_h<2, true>,
                         cudaFuncAttributeMaxDynamicSharedMemorySize, HGSMEM);
    cudaFuncSetAttribute(gemm_h<1, false>,
                         cudaFuncAttributeMaxDynamicSharedMemorySize, HGSMEM);
    cudaFuncSetAttribute(attn_mma,
                         cudaFuncAttributeMaxDynamicSharedMemorySize, AT_SMEM);

    // one-time fp16 conversions
    cvt_w_t<<<dim3(INNER / 32, CHN / 32), 256>>>(wq, p_wq16, CHN, INNER);
    cvt_w_t<<<dim3(INNER / 32, XDIM / 32), 256>>>(wk, p_wk16, XDIM, INNER);
    cvt_w_t<<<dim3(INNER / 32, XDIM / 32), 256>>>(wv, p_wv16, XDIM, INNER);
    cvt_w_t<<<dim3(CHN / 32, INNER / 32), 256>>>(wo, p_wo16, INNER, CHN);
    {
        int n = BATCH * TT * XDIM;
        cvt16<<<(n + 255) / 256, 256>>>(enc, p_e16, n);
    }

    // LN stats + normalize/transpose to fp16 [b][s][c]
    ln_stats<<<dim3(SP / 256, BATCH), 256>>>(hs);
    ln_t16<<<dim3(SP / 32, CHN / 32, BATCH), 256>>>(hs, lnw, lnb);

    // Q = x16 @ wq16^T  (fp16 out)
    gemm_h<2, false><<<dim3(INNER / 128, (BATCH * SP) / 128), 256, HGSMEM>>>(
        p_x16, p_wq16, p_q16, BATCH * SP, INNER, CHN, CHN, nullptr, nullptr);

    // K, V = e16 @ w^T  (fp16 out, M = 1232 guarded)
    int mkv = (BATCH * TT + 127) / 128;
    gemm_h<2, true><<<dim3(INNER / 128, mkv), 256, HGSMEM>>>(
        p_e16, p_wk16, p_k16, BATCH * TT, INNER, XDIM, XDIM, nullptr, nullptr);
    gemm_h<2, true><<<dim3(INNER / 128, mkv), 256, HGSMEM>>>(
        p_e16, p_wv16, p_v16, BATCH * TT, INNER, XDIM, XDIM, nullptr, nullptr);

    // attention (fp16 tensor-core)
    attn_mma<<<dim3(SP / 128, NHE, BATCH), 256, AT_SMEM>>>();

    // out = at16 @ wo16^T + bo + residual (transposed store, fp32)
    gemm_h<1, false><<<dim3(CHN / 128, (BATCH * SP) / 128), 256, HGSMEM>>>(
        p_at16, p_wo16, out, BATCH * SP, CHN, INNER, INNER, bo, hs);
}

// round 9
// speedup vs baseline: 1.3969x; 1.3969x over previous
#include <cuda_runtime.h>
#include <cuda_fp16.h>
#include <math.h>
#include <stdint.h>

#define BATCH 16
#define CHN   640
#define SP    4096
#define TT    77
#define XDIM  768
#define NHE   8
#define HDIM  80
#define INNER 640

// ---------------- scratch ----------------
__device__ float  g_q   [(size_t)BATCH * SP * INNER];   // fp32 (attn input)
__device__ float  g_k   [(size_t)BATCH * TT * INNER];
__device__ float  g_v   [(size_t)BATCH * TT * INNER];
__device__ __half g_x16 [(size_t)BATCH * SP * CHN];     // LN(hs) [b][s][c]
__device__ __half g_at16[(size_t)BATCH * SP * INNER];   // attn out
__device__ __half g_e16 [(size_t)BATCH * TT * XDIM];
__device__ __half g_wq16[(size_t)INNER * CHN];          // [N][K]
__device__ __half g_wk16[(size_t)INNER * XDIM];
__device__ __half g_wv16[(size_t)INNER * XDIM];
__device__ __half g_wo16[(size_t)CHN * INNER];
__device__ float  g_mu  [(size_t)BATCH * SP];
__device__ float  g_rs  [(size_t)BATCH * SP];

// ---------------- helpers ----------------
__device__ __forceinline__ uint32_t smem_u32(const void* p) {
    uint32_t a;
    asm("{ .reg .u64 t; cvta.to.shared.u64 t, %1; cvt.u32.u64 %0, t; }"
        : "=r"(a) : "l"(p));
    return a;
}
__device__ __forceinline__ void cp16(uint32_t dst, const void* src, bool v) {
    int sz = v ? 16 : 0;
    asm volatile("cp.async.cg.shared.global [%0], [%1], 16, %2;"
                 :: "r"(dst), "l"(src), "r"(sz) : "memory");
}
#define CP_COMMIT() asm volatile("cp.async.commit_group;" ::: "memory")
#define CP_WAIT0()  asm volatile("cp.async.wait_group 0;" ::: "memory")

__device__ __forceinline__ void mma_tf32(float c[4], unsigned a0, unsigned a1,
                                         unsigned a2, unsigned a3,
                                         unsigned b0, unsigned b1)
{
    asm volatile(
        "mma.sync.aligned.m16n8k8.row.col.f32.tf32.tf32.f32 "
        "{%0,%1,%2,%3},{%4,%5,%6,%7},{%8,%9},{%0,%1,%2,%3};"
        : "+f"(c[0]), "+f"(c[1]), "+f"(c[2]), "+f"(c[3])
        : "r"(a0), "r"(a1), "r"(a2), "r"(a3), "r"(b0), "r"(b1));
}
__device__ __forceinline__ void mma_f16(float c[4], unsigned a0, unsigned a1,
                                        unsigned a2, unsigned a3,
                                        unsigned b0, unsigned b1)
{
    asm volatile(
        "mma.sync.aligned.m16n8k16.row.col.f32.f16.f16.f32 "
        "{%0,%1,%2,%3},{%4,%5,%6,%7},{%8,%9},{%0,%1,%2,%3};"
        : "+f"(c[0]), "+f"(c[1]), "+f"(c[2]), "+f"(c[3])
        : "r"(a0), "r"(a1), "r"(a2), "r"(a3), "r"(b0), "r"(b1));
}

// ---------------- LN stats ----------------
__global__ void __launch_bounds__(256) ln_stats(const float* __restrict__ x)
{
    int s = blockIdx.x * 256 + threadIdx.x;
    int b = blockIdx.y;
    const float* xp = x + (size_t)b * CHN * SP + s;
    float sum = 0.f, sumsq = 0.f;
    for (int c = 0; c < CHN; c++) { float v = xp[(size_t)c * SP]; sum += v; sumsq += v * v; }
    float mu = sum * (1.0f / CHN);
    float var = sumsq * (1.0f / CHN) - mu * mu;
    g_mu[(size_t)b * SP + s] = mu;
    g_rs[(size_t)b * SP + s] = rsqrtf(var + 1e-6f);
}

// ---------------- normalize + transpose -> fp16 [b][s][c] ----------------
__global__ void __launch_bounds__(256) ln_t16(const float* __restrict__ x,
                                              const float* __restrict__ lw,
                                              const float* __restrict__ lb)
{
    __shared__ float t[32][33];
    int s0 = blockIdx.x * 32, c0 = blockIdx.y * 32, b = blockIdx.z;
    int xl = threadIdx.x & 31, y = (threadIdx.x >> 5) * 4;
#pragma unroll
    for (int i = 0; i < 4; i++)
        t[y + i][xl] = x[((size_t)b * CHN + c0 + y + i) * SP + s0 + xl];
    __syncthreads();
    float wv = lw[c0 + xl], bv = lb[c0 + xl];
#pragma unroll
    for (int i = 0; i < 4; i++) {
        int s = s0 + y + i;
        float mu = g_mu[(size_t)b * SP + s];
        float rs = g_rs[(size_t)b * SP + s];
        float v = (t[xl][y + i] - mu) * rs * wv + bv;
        g_x16[((size_t)b * SP + s) * CHN + c0 + xl] = __float2half_rn(v);
    }
}

// ---------------- weight transpose+cvt [R][C] fp32 -> [C][R] fp16 ----------------
__global__ void __launch_bounds__(256) cvt_w_t(const float* __restrict__ in,
                                               __half* __restrict__ out, int R, int C)
{
    __shared__ float t[32][33];
    int c0 = blockIdx.x * 32, r0 = blockIdx.y * 32;
    int xl = threadIdx.x & 31, y = (threadIdx.x >> 5) * 4;
#pragma unroll
    for (int i = 0; i < 4; i++)
        t[y + i][xl] = in[(size_t)(r0 + y + i) * C + c0 + xl];
    __syncthreads();
#pragma unroll
    for (int i = 0; i < 4; i++)
        out[(size_t)(c0 + y + i) * R + r0 + xl] = __float2half_rn(t[xl][y + i]);
}

// ---------------- elementwise cvt ----------------
__global__ void __launch_bounds__(256) cvt16(const float* __restrict__ in,
                                             __half* __restrict__ out, int n)
{
    int i = blockIdx.x * 256 + threadIdx.x;
    if (i < n) out[i] = __float2half_rn(in[i]);
}

// ---------------- fp16 mma GEMM: D = A[M][K] * Bt[N][K]^T ----------------
// 2-stage cp.async pipeline -> 40960B smem -> 2 CTAs/SM truly resident.
// EPI 0: C[m][n] fp32;  EPI 1: out[b][n][s] fp32 + bias + resid
#define HBOFF  10240
#define HSTG   20480
#define HGSMEM (2 * HSTG)     // 40960

template<int EPI, bool MG>
__global__ void __launch_bounds__(256, 2)
gemm_h(const __half* __restrict__ A, const __half* __restrict__ Bt,
       float* __restrict__ Cout, int M, int N, int K, int lda,
       const float* __restrict__ bias, const float* __restrict__ resid)
{
    extern __shared__ char smc[];
    uint32_t sb = smem_u32(smc);

    int tid = threadIdx.x, lane = tid & 31, w = tid >> 5;
    int r = lane >> 2, q = lane & 3;
    int wm = w & 3, wn = w >> 2;
    int m0 = blockIdx.y * 128;
    int n0 = blockIdx.x * 128;
    int mb = wm * 32, nb = wn * 64;
    int NT = K >> 5;

    float acc[2][8][4];
#pragma unroll
    for (int i = 0; i < 2; i++)
#pragma unroll
        for (int j = 0; j < 8; j++)
#pragma unroll
            for (int l = 0; l < 4; l++) acc[i][j][l] = 0.f;

    auto load_stage = [&](int slot, int k0) {
        uint32_t st = sb + slot * HSTG;
#pragma unroll
        for (int i = 0; i < 2; i++) {
            int cid = tid + i * 256;
            int row = cid >> 2, ch = cid & 3;
            bool v = !MG || (m0 + row) < M;
            cp16(st + row * 80 + ch * 16,
                 A + (size_t)(m0 + row) * lda + k0 + ch * 8, v);
        }
#pragma unroll
        for (int i = 0; i < 2; i++) {
            int cid = tid + i * 256;
            int row = cid >> 2, ch = cid & 3;
            cp16(st + HBOFF + row * 80 + ch * 16,
                 Bt + (size_t)(n0 + row) * K + k0 + ch * 8, true);
        }
    };

    auto lda_frag = [&](unsigned af[2][4], const __half* As, int kb) {
        int kof = kb + 2 * q;
#pragma unroll
        for (int im = 0; im < 2; im++) {
            int mrow = mb + im * 16 + r;
            af[im][0] = *(const unsigned*)&As[mrow * 40 + kof];
            af[im][1] = *(const unsigned*)&As[(mrow + 8) * 40 + kof];
            af[im][2] = *(const unsigned*)&As[mrow * 40 + kof + 8];
            af[im][3] = *(const unsigned*)&As[(mrow + 8) * 40 + kof + 8];
        }
    };

    load_stage(0, 0); CP_COMMIT();

    for (int t = 0; t < NT; t++) {
        CP_WAIT0();
        __syncthreads();
        if (t + 1 < NT) { load_stage((t + 1) & 1, (t + 1) * 32); CP_COMMIT(); }

        int slot = t & 1;
        const __half* As = (const __half*)(smc + slot * HSTG);
        const __half* Bs = (const __half*)(smc + slot * HSTG + HBOFF);

        unsigned ac[2][4], an[2][4];
        lda_frag(ac, As, 0);
#pragma unroll
        for (int kc = 0; kc < 2; kc++) {
            if (kc == 0) lda_frag(an, As, 16);
            int kof = kc * 16 + 2 * q;
#pragma unroll
            for (int half_ = 0; half_ < 2; half_++) {
                unsigned bb[4][2];
#pragma unroll
                for (int i = 0; i < 4; i++) {
                    int ncol = nb + (half_ * 4 + i) * 8 + r;
                    bb[i][0] = *(const unsigned*)&Bs[ncol * 40 + kof];
                    bb[i][1] = *(const unsigned*)&Bs[ncol * 40 + kof + 8];
                }
#pragma unroll
                for (int i = 0; i < 4; i++) {
                    int in_ = half_ * 4 + i;
#pragma unroll
                    for (int im = 0; im < 2; im++)
                        mma_f16(acc[im][in_], ac[im][0], ac[im][1], ac[im][2],
                                ac[im][3], bb[i][0], bb[i][1]);
                }
            }
            if (kc == 0) {
#pragma unroll
                for (int im = 0; im < 2; im++)
#pragma unroll
                    for (int j = 0; j < 4; j++) ac[im][j] = an[im][j];
            }
        }
    }
    __syncthreads();

    // -------- epilogue --------
    float* Cs = (float*)smc;
    if (EPI == 0) {
#pragma unroll 1
        for (int ch = 0; ch < 4; ch++) {
            __syncthreads();
            if (wm == ch) {
#pragma unroll
                for (int im = 0; im < 2; im++) {
                    int r0 = im * 16 + r;
#pragma unroll
                    for (int in_ = 0; in_ < 8; in_++) {
                        int cc = nb + in_ * 8 + q * 2;
                        Cs[r0 * 132 + cc]           = acc[im][in_][0];
                        Cs[r0 * 132 + cc + 1]       = acc[im][in_][1];
                        Cs[(r0 + 8) * 132 + cc]     = acc[im][in_][2];
                        Cs[(r0 + 8) * 132 + cc + 1] = acc[im][in_][3];
                    }
                }
            }
            __syncthreads();
            for (int t = tid; t < 32 * 128; t += 256) {
                int ml = t >> 7, n = t & 127;
                int m = m0 + ch * 32 + ml;
                if (MG && m >= M) continue;
                Cout[(size_t)m * N + n0 + n] = Cs[ml * 132 + n];
            }
        }
    } else {
#pragma unroll 1
        for (int ch = 0; ch < 4; ch++) {
            __syncthreads();
            if (wn == (ch >> 1)) {
                int inlo = (ch & 1) * 4;
#pragma unroll
                for (int im = 0; im < 2; im++) {
                    int mrow = mb + im * 16 + r;
#pragma unroll
                    for (int ii = 0; ii < 4; ii++) {
                        int in_ = inlo + ii;
                        int nl = in_ * 8 + q * 2 - (ch & 1) * 32;
                        Cs[nl * 132 + mrow]           = acc[im][in_][0];
                        Cs[(nl + 1) * 132 + mrow]     = acc[im][in_][1];
                        Cs[nl * 132 + mrow + 8]       = acc[im][in_][2];
                        Cs[(nl + 1) * 132 + mrow + 8] = acc[im][in_][3];
                    }
                }
            }
            __syncthreads();
            for (int t = tid; t < 32 * 128; t += 256) {
                int nl = t >> 7, ml = t & 127;
                int n = n0 + ch * 32 + nl;
                int m = m0 + ml;
                int b = m >> 12, s = m & (SP - 1);
                size_t addr = (size_t)b * CHN * SP + (size_t)n * SP + s;
                Cout[addr] = Cs[nl * 132 + ml] + bias[n] + resid[addr];
            }
        }
    }
}

// ---------------- tensor-core attention (tf32), half2 output ----------------
#define AT_SMEM 55040

__global__ void __launch_bounds__(256, 2) attn_mma()
{
    extern __shared__ float sm[];
    float* Ks = sm;              // [80][84]
    float* Vs = sm + 6720;       // [80][88]

    int tid = threadIdx.x, lane = tid & 31, w = tid >> 5;
    int b = blockIdx.z, h = blockIdx.y;
    int q0 = blockIdx.x * 128;
    int mb = w * 16;
    int r = lane >> 2, q = lane & 3, q2 = q * 2;
    uint32_t sb = smem_u32(sm);

    const float* kg = g_k + (size_t)b * TT * INNER + h * HDIM;
    const float* vg = g_v + (size_t)b * TT * INNER + h * HDIM;

#pragma unroll
    for (int i = 0; i < 7; i++) {
        int cid = tid + i * 256;
        if (cid < 1540) {
            int row = cid / 20, ch = cid % 20;
            cp16(sb + (row * 84 + ch * 4) * 4, kg + (size_t)row * INNER + ch * 4, true);
            cp16(sb + (6720 + row * 88 + ch * 4) * 4, vg + (size_t)row * INNER + ch * 4, true);
        }
    }
    CP_COMMIT();

    const float* qg = g_q + ((size_t)b * SP + q0 + mb) * INNER + h * HDIM;
    float qf[10][4];
#pragma unroll
    for (int k8 = 0; k8 < 10; k8++) {
        int c = k8 * 8 + q;
        qf[k8][0] = qg[(size_t)r * INNER + c];
        qf[k8][1] = qg[(size_t)(r + 8) * INNER + c];
        qf[k8][2] = qg[(size_t)r * INNER + c + 4];
        qf[k8][3] = qg[(size_t)(r + 8) * INNER + c + 4];
    }

    if (tid < 240) {
        int row = 77 + tid / 80, col = tid % 80;
        Ks[row * 84 + col] = 0.f;
        Vs[row * 88 + col] = 0.f;
    }
    CP_WAIT0();
    __syncthreads();

    float acc[10][4];
#pragma unroll
    for (int i = 0; i < 10; i++)
#pragma unroll
        for (int j = 0; j < 4; j++) acc[i][j] = 0.f;

#pragma unroll
    for (int k8 = 0; k8 < 10; k8++) {
        int kr = k8 * 8 + q;
        unsigned a0 = __float_as_uint(qf[k8][0]);
        unsigned a1 = __float_as_uint(qf[k8][1]);
        unsigned a2 = __float_as_uint(qf[k8][2]);
        unsigned a3 = __float_as_uint(qf[k8][3]);
#pragma unroll
        for (int in_ = 0; in_ < 10; in_++) {
            int tcol = in_ * 8 + r;
            unsigned b0 = __float_as_uint(Ks[tcol * 84 + kr]);
            unsigned b1 = __float_as_uint(Ks[tcol * 84 + kr + 4]);
            mma_tf32(acc[in_], a0, a1, a2, a3, b0, b1);
        }
    }

    const float scale = 0.11180339887498949f;
    float invs[2];
#pragma unroll
    for (int hf = 0; hf < 2; hf++) {
        float mx = -1e30f;
#pragma unroll
        for (int in_ = 0; in_ < 10; in_++) {
            int c0 = in_ * 8 + q2;
            float v0 = (c0     < TT) ? acc[in_][hf * 2]     * scale : -1e30f;
            float v1 = (c0 + 1 < TT) ? acc[in_][hf * 2 + 1] * scale : -1e30f;
            acc[in_][hf * 2] = v0; acc[in_][hf * 2 + 1] = v1;
            mx = fmaxf(mx, fmaxf(v0, v1));
        }
        mx = fmaxf(mx, __shfl_xor_sync(0xffffffffu, mx, 1));
        mx = fmaxf(mx, __shfl_xor_sync(0xffffffffu, mx, 2));
        float s = 0.f;
#pragma unroll
        for (int in_ = 0; in_ < 10; in_++) {
            int c0 = in_ * 8 + q2;
            float e0 = (c0     < TT) ? __expf(acc[in_][hf * 2]     - mx) : 0.f;
            float e1 = (c0 + 1 < TT) ? __expf(acc[in_][hf * 2 + 1] - mx) : 0.f;
            acc[in_][hf * 2] = e0; acc[in_][hf * 2 + 1] = e1;
            s += e0 + e1;
        }
        s += __shfl_xor_sync(0xffffffffu, s, 1);
        s += __shfl_xor_sync(0xffffffffu, s, 2);
        invs[hf] = 1.f / s;
    }

    float oc[10][4];
#pragma unroll
    for (int i = 0; i < 10; i++)
#pragma unroll
        for (int j = 0; j < 4; j++) oc[i][j] = 0.f;

    int S0 = (r << 2) | (q >> 1);
    int S2 = S0 + 2;
    bool odd = (q & 1) != 0;
#pragma unroll
    for (int k8 = 0; k8 < 10; k8++) {
        float v0 = __shfl_sync(0xffffffffu, acc[k8][0], S0);
        float v1 = __shfl_sync(0xffffffffu, acc[k8][1], S0);
        float v2 = __shfl_sync(0xffffffffu, acc[k8][2], S0);
        float v3 = __shfl_sync(0xffffffffu, acc[k8][3], S0);
        float u0 = __shfl_sync(0xffffffffu, acc[k8][0], S2);
        float u1 = __shfl_sync(0xffffffffu, acc[k8][1], S2);
        float u2 = __shfl_sync(0xffffffffu, acc[k8][2], S2);
        float u3 = __shfl_sync(0xffffffffu, acc[k8][3], S2);
        unsigned a0 = __float_as_uint(odd ? v1 : v0);
        unsigned a1 = __float_as_uint(odd ? v3 : v2);
        unsigned a2 = __float_as_uint(odd ? u1 : u0);
        unsigned a3 = __float_as_uint(odd ? u3 : u2);
        int kr = k8 * 8 + q;
#pragma unroll
        for (int in_ = 0; in_ < 10; in_++) {
            int ncol = in_ * 8 + r;
            unsigned b0 = __float_as_uint(Vs[kr * 88 + ncol]);
            unsigned b1 = __float_as_uint(Vs[(kr + 4) * 88 + ncol]);
            mma_tf32(oc[in_], a0, a1, a2, a3, b0, b1);
        }
    }

    __half* og = g_at16 + ((size_t)b * SP + q0 + mb) * INNER + h * HDIM;
#pragma unroll
    for (int in_ = 0; in_ < 10; in_++) {
        int c = in_ * 8 + q2;
        *(__half2*)(og + (size_t)r * INNER + c) =
            __floats2half2_rn(oc[in_][0] * invs[0], oc[in_][1] * invs[0]);
        *(__half2*)(og + (size_t)(r + 8) * INNER + c) =
            __floats2half2_rn(oc[in_][2] * invs[1], oc[in_][3] * invs[1]);
    }
}

// ---------------- launch ----------------
extern "C" void kernel_launch(void* const* d_in, const int* in_sizes, int n_in,
                              void* d_out, int out_size)
{
    (void)in_sizes; (void)n_in; (void)out_size;
    const float* hs  = (const float*)d_in[0];
    const float* enc = (const float*)d_in[1];
    const float* lnw = (const float*)d_in[2];
    const float* lnb = (const float*)d_in[3];
    const float* wq  = (const float*)d_in[4];
    const float* wk  = (const float*)d_in[5];
    const float* wv  = (const float*)d_in[6];
    const float* wo  = (const float*)d_in[7];
    const float* bo  = (const float*)d_in[8];
    float* out = (float*)d_out;

    float *p_q, *p_k, *p_v;
    __half *p_x16, *p_at16, *p_e16, *p_wq16, *p_wk16, *p_wv16, *p_wo16;
    cudaGetSymbolAddress((void**)&p_q,    g_q);
    cudaGetSymbolAddress((void**)&p_k,    g_k);
    cudaGetSymbolAddress((void**)&p_v,    g_v);
    cudaGetSymbolAddress((void**)&p_x16,  g_x16);
    cudaGetSymbolAddress((void**)&p_at16, g_at16);
    cudaGetSymbolAddress((void**)&p_e16,  g_e16);
    cudaGetSymbolAddress((void**)&p_wq16, g_wq16);
    cudaGetSymbolAddress((void**)&p_wk16, g_wk16);
    cudaGetSymbolAddress((void**)&p_wv16, g_wv16);
    cudaGetSymbolAddress((void**)&p_wo16, g_wo16);

    cudaFuncSetAttribute(gemm_h<0, false>,
                         cudaFuncAttributeMaxDynamicSharedMemorySize, HGSMEM);
    cudaFuncSetAttribute(gemm_h<0, true>,
                         cudaFuncAttributeMaxDynamicSharedMemorySize, HGSMEM);
    cudaFuncSetAttribute(gemm_h<1, false>,
                         cudaFuncAttributeMaxDynamicSharedMemorySize, HGSMEM);
    cudaFuncSetAttribute(attn_mma,
                         cudaFuncAttributeMaxDynamicSharedMemorySize, AT_SMEM);

    // one-time fp16 conversions
    cvt_w_t<<<dim3(INNER / 32, CHN / 32), 256>>>(wq, p_wq16, CHN, INNER);
    cvt_w_t<<<dim3(INNER / 32, XDIM / 32), 256>>>(wk, p_wk16, XDIM, INNER);
    cvt_w_t<<<dim3(INNER / 32, XDIM / 32), 256>>>(wv, p_wv16, XDIM, INNER);
    cvt_w_t<<<dim3(CHN / 32, INNER / 32), 256>>>(wo, p_wo16, INNER, CHN);
    {
        int n = BATCH * TT * XDIM;
        cvt16<<<(n + 255) / 256, 256>>>(enc, p_e16, n);
    }

    // LN stats + normalize/transpose to fp16 [b][s][c]
    ln_stats<<<dim3(SP / 256, BATCH), 256>>>(hs);
    ln_t16<<<dim3(SP / 32, CHN / 32, BATCH), 256>>>(hs, lnw, lnb);

    // Q = x16 @ wq16^T (fp32 out)
    gemm_h<0, false><<<dim3(INNER / 128, (BATCH * SP) / 128), 256, HGSMEM>>>(
        p_x16, p_wq16, p_q, BATCH * SP, INNER, CHN, CHN, nullptr, nullptr);

    // K, V = e16 @ w^T   (M = 1232, guarded)
    int mkv = (BATCH * TT + 127) / 128;
    gemm_h<0, true><<<dim3(INNER / 128, mkv), 256, HGSMEM>>>(
        p_e16, p_wk16, p_k, BATCH * TT, INNER, XDIM, XDIM, nullptr, nullptr);
    gemm_h<0, true><<<dim3(INNER / 128, mkv), 256, HGSMEM>>>(
        p_e16, p_wv16, p_v, BATCH * TT, INNER, XDIM, XDIM, nullptr, nullptr);

    // attention (tf32 tensor-core)
    attn_mma<<<dim3(SP / 128, NHE, BATCH), 256, AT_SMEM>>>();

    // out = at16 @ wo16^T + bo + residual (transposed store, fp32)
    gemm_h<1, false><<<dim3(CHN / 128, (BATCH * SP) / 128), 256, HGSMEM>>>(
        p_at16, p_wo16, out, BATCH * SP, CHN, INNER, INNER, bo, hs);
}

// round 10
// speedup vs baseline: 1.4438x; 1.0336x over previous
#include <cuda_runtime.h>
#include <cuda_fp16.h>
#include <math.h>
#include <stdint.h>

#define BATCH 16
#define CHN   640
#define SP    4096
#define TT    77
#define XDIM  768
#define NHE   8
#define HDIM  80
#define INNER 640

// ---------------- scratch ----------------
__device__ float  g_q   [(size_t)BATCH * SP * INNER];   // fp32 (attn input)
__device__ float  g_k   [(size_t)BATCH * TT * INNER];
__device__ float  g_v   [(size_t)BATCH * TT * INNER];
__device__ __half g_x16 [(size_t)BATCH * SP * CHN];     // LN(hs) [b][s][c]
__device__ __half g_at16[(size_t)BATCH * SP * INNER];   // attn out
__device__ __half g_e16 [(size_t)BATCH * TT * XDIM];
__device__ __half g_wq16[(size_t)INNER * CHN];          // [N][K]
__device__ __half g_wk16[(size_t)INNER * XDIM];
__device__ __half g_wv16[(size_t)INNER * XDIM];
__device__ __half g_wo16[(size_t)CHN * INNER];
__device__ float  g_mu  [(size_t)BATCH * SP];
__device__ float  g_rs  [(size_t)BATCH * SP];

// ---------------- helpers ----------------
__device__ __forceinline__ uint32_t smem_u32(const void* p) {
    uint32_t a;
    asm("{ .reg .u64 t; cvta.to.shared.u64 t, %1; cvt.u32.u64 %0, t; }"
        : "=r"(a) : "l"(p));
    return a;
}
__device__ __forceinline__ void cp16(uint32_t dst, const void* src, bool v) {
    int sz = v ? 16 : 0;
    asm volatile("cp.async.cg.shared.global [%0], [%1], 16, %2;"
                 :: "r"(dst), "l"(src), "r"(sz) : "memory");
}
#define CP_COMMIT() asm volatile("cp.async.commit_group;" ::: "memory")
#define CP_WAIT1()  asm volatile("cp.async.wait_group 1;" ::: "memory")
#define CP_WAIT0()  asm volatile("cp.async.wait_group 0;" ::: "memory")

__device__ __forceinline__ void ldsm4(unsigned r[4], uint32_t a) {
    asm volatile("ldmatrix.sync.aligned.m8n8.x4.shared.b16 {%0,%1,%2,%3}, [%4];"
                 : "=r"(r[0]), "=r"(r[1]), "=r"(r[2]), "=r"(r[3]) : "r"(a));
}

__device__ __forceinline__ void mma_tf32(float c[4], unsigned a0, unsigned a1,
                                         unsigned a2, unsigned a3,
                                         unsigned b0, unsigned b1)
{
    asm volatile(
        "mma.sync.aligned.m16n8k8.row.col.f32.tf32.tf32.f32 "
        "{%0,%1,%2,%3},{%4,%5,%6,%7},{%8,%9},{%0,%1,%2,%3};"
        : "+f"(c[0]), "+f"(c[1]), "+f"(c[2]), "+f"(c[3])
        : "r"(a0), "r"(a1), "r"(a2), "r"(a3), "r"(b0), "r"(b1));
}
__device__ __forceinline__ void mma_f16(float c[4], unsigned a0, unsigned a1,
                                        unsigned a2, unsigned a3,
                                        unsigned b0, unsigned b1)
{
    asm volatile(
        "mma.sync.aligned.m16n8k16.row.col.f32.f16.f16.f32 "
        "{%0,%1,%2,%3},{%4,%5,%6,%7},{%8,%9},{%0,%1,%2,%3};"
        : "+f"(c[0]), "+f"(c[1]), "+f"(c[2]), "+f"(c[3])
        : "r"(a0), "r"(a1), "r"(a2), "r"(a3), "r"(b0), "r"(b1));
}

// ---------------- LN stats ----------------
__global__ void __launch_bounds__(256) ln_stats(const float* __restrict__ x)
{
    int s = blockIdx.x * 256 + threadIdx.x;
    int b = blockIdx.y;
    const float* xp = x + (size_t)b * CHN * SP + s;
    float sum = 0.f, sumsq = 0.f;
    for (int c = 0; c < CHN; c++) { float v = xp[(size_t)c * SP]; sum += v; sumsq += v * v; }
    float mu = sum * (1.0f / CHN);
    float var = sumsq * (1.0f / CHN) - mu * mu;
    g_mu[(size_t)b * SP + s] = mu;
    g_rs[(size_t)b * SP + s] = rsqrtf(var + 1e-6f);
}

// ---------------- normalize + transpose -> fp16 [b][s][c] ----------------
__global__ void __launch_bounds__(256) ln_t16(const float* __restrict__ x,
                                              const float* __restrict__ lw,
                                              const float* __restrict__ lb)
{
    __shared__ float t[32][33];
    int s0 = blockIdx.x * 32, c0 = blockIdx.y * 32, b = blockIdx.z;
    int xl = threadIdx.x & 31, y = (threadIdx.x >> 5) * 4;
#pragma unroll
    for (int i = 0; i < 4; i++)
        t[y + i][xl] = x[((size_t)b * CHN + c0 + y + i) * SP + s0 + xl];
    __syncthreads();
    float wv = lw[c0 + xl], bv = lb[c0 + xl];
#pragma unroll
    for (int i = 0; i < 4; i++) {
        int s = s0 + y + i;
        float mu = g_mu[(size_t)b * SP + s];
        float rs = g_rs[(size_t)b * SP + s];
        float v = (t[xl][y + i] - mu) * rs * wv + bv;
        g_x16[((size_t)b * SP + s) * CHN + c0 + xl] = __float2half_rn(v);
    }
}

// ---------------- weight transpose+cvt [R][C] fp32 -> [C][R] fp16 ----------------
__global__ void __launch_bounds__(256) cvt_w_t(const float* __restrict__ in,
                                               __half* __restrict__ out, int R, int C)
{
    __shared__ float t[32][33];
    int c0 = blockIdx.x * 32, r0 = blockIdx.y * 32;
    int xl = threadIdx.x & 31, y = (threadIdx.x >> 5) * 4;
#pragma unroll
    for (int i = 0; i < 4; i++)
        t[y + i][xl] = in[(size_t)(r0 + y + i) * C + c0 + xl];
    __syncthreads();
#pragma unroll
    for (int i = 0; i < 4; i++)
        out[(size_t)(c0 + y + i) * R + r0 + xl] = __float2half_rn(t[xl][y + i]);
}

// ---------------- elementwise cvt ----------------
__global__ void __launch_bounds__(256) cvt16(const float* __restrict__ in,
                                             __half* __restrict__ out, int n)
{
    int i = blockIdx.x * 256 + threadIdx.x;
    if (i < n) out[i] = __float2half_rn(in[i]);
}

// ---------------- fp16 mma GEMM: D = A[M][K] * Bt[N][K]^T ----------------
// 3-stage cp.async pipeline; fragments via ldmatrix.x4 (conflict-free, pitch 40h).
// EPI 0: C[m][n] fp32;  EPI 1: out[b][n][s] fp32 + bias + resid
#define HBOFF  10240
#define HSTG   20480
#define HGSMEM (3 * HSTG)

template<int EPI, bool MG>
__global__ void __launch_bounds__(256, 2)
gemm_h(const __half* __restrict__ A, const __half* __restrict__ Bt,
       float* __restrict__ Cout, int M, int N, int K, int lda,
       const float* __restrict__ bias, const float* __restrict__ resid)
{
    extern __shared__ char smc[];
    uint32_t sb = smem_u32(smc);

    int tid = threadIdx.x, lane = tid & 31, w = tid >> 5;
    int r = lane >> 2, q = lane & 3;
    int wm = w & 3, wn = w >> 2;
    int m0 = blockIdx.y * 128;
    int n0 = blockIdx.x * 128;
    int mb = wm * 32, nb = wn * 64;
    int NT = K >> 5;

    // ldmatrix per-lane byte offsets (pitch = 40 halves = 80 B)
    uint32_t offA = (uint32_t)((mb + (lane & 15)) * 40 + ((lane & 16) ? 8 : 0)) * 2;
    uint32_t offB = (uint32_t)((nb + (lane & 7) + ((lane & 16) ? 8 : 0)) * 40
                               + ((lane & 8) ? 8 : 0)) * 2;

    float acc[2][8][4];
#pragma unroll
    for (int i = 0; i < 2; i++)
#pragma unroll
        for (int j = 0; j < 8; j++)
#pragma unroll
            for (int l = 0; l < 4; l++) acc[i][j][l] = 0.f;

    auto load_stage = [&](int slot, int k0) {
        uint32_t st = sb + slot * HSTG;
#pragma unroll
        for (int i = 0; i < 2; i++) {
            int cid = tid + i * 256;
            int row = cid >> 2, ch = cid & 3;
            bool v = !MG || (m0 + row) < M;
            cp16(st + row * 80 + ch * 16,
                 A + (size_t)(m0 + row) * lda + k0 + ch * 8, v);
        }
#pragma unroll
        for (int i = 0; i < 2; i++) {
            int cid = tid + i * 256;
            int row = cid >> 2, ch = cid & 3;
            cp16(st + HBOFF + row * 80 + ch * 16,
                 Bt + (size_t)(n0 + row) * K + k0 + ch * 8, true);
        }
    };

    load_stage(0, 0);  CP_COMMIT();
    load_stage(1, 32); CP_COMMIT();

    for (int t = 0; t < NT; t++) {
        if (t == NT - 1) CP_WAIT0(); else CP_WAIT1();
        __syncthreads();
        if (t + 2 < NT) { load_stage((t + 2) % 3, (t + 2) * 32); CP_COMMIT(); }

        int slot = t % 3;
        uint32_t aBase = sb + slot * HSTG + offA;
        uint32_t bBase = sb + slot * HSTG + HBOFF + offB;

        unsigned ac[2][4], an[2][4];
        ldsm4(ac[0], aBase);             // im0, k 0..15
        ldsm4(ac[1], aBase + 1280);      // im1 (16 rows * 80B)
#pragma unroll
        for (int kc = 0; kc < 2; kc++) {
            if (kc == 0) {
                ldsm4(an[0], aBase + 32);           // k 16..31
                ldsm4(an[1], aBase + 1280 + 32);
            }
            unsigned bb[4][4];
#pragma unroll
            for (int j = 0; j < 4; j++)
                ldsm4(bb[j], bBase + j * 1280 + kc * 32);
#pragma unroll
            for (int j = 0; j < 4; j++) {
#pragma unroll
                for (int im = 0; im < 2; im++)
                    mma_f16(acc[im][2 * j], ac[im][0], ac[im][1], ac[im][2],
                            ac[im][3], bb[j][0], bb[j][1]);
#pragma unroll
                for (int im = 0; im < 2; im++)
                    mma_f16(acc[im][2 * j + 1], ac[im][0], ac[im][1], ac[im][2],
                            ac[im][3], bb[j][2], bb[j][3]);
            }
            if (kc == 0) {
#pragma unroll
                for (int im = 0; im < 2; im++)
#pragma unroll
                    for (int jj = 0; jj < 4; jj++) ac[im][jj] = an[im][jj];
            }
        }
    }
    __syncthreads();

    // -------- epilogue --------
    float* Cs = (float*)smc;
    if (EPI == 0) {
#pragma unroll 1
        for (int ch = 0; ch < 4; ch++) {
            __syncthreads();
            if (wm == ch) {
#pragma unroll
                for (int im = 0; im < 2; im++) {
                    int r0 = im * 16 + r;
#pragma unroll
                    for (int in_ = 0; in_ < 8; in_++) {
                        int cc = nb + in_ * 8 + q * 2;
                        Cs[r0 * 132 + cc]           = acc[im][in_][0];
                        Cs[r0 * 132 + cc + 1]       = acc[im][in_][1];
                        Cs[(r0 + 8) * 132 + cc]     = acc[im][in_][2];
                        Cs[(r0 + 8) * 132 + cc + 1] = acc[im][in_][3];
                    }
                }
            }
            __syncthreads();
            for (int t = tid; t < 32 * 128; t += 256) {
                int ml = t >> 7, n = t & 127;
                int m = m0 + ch * 32 + ml;
                if (MG && m >= M) continue;
                Cout[(size_t)m * N + n0 + n] = Cs[ml * 132 + n];
            }
        }
    } else {
#pragma unroll 1
        for (int ch = 0; ch < 4; ch++) {
            __syncthreads();
            if (wn == (ch >> 1)) {
                int inlo = (ch & 1) * 4;
#pragma unroll
                for (int im = 0; im < 2; im++) {
                    int mrow = mb + im * 16 + r;
#pragma unroll
                    for (int ii = 0; ii < 4; ii++) {
                        int in_ = inlo + ii;
                        int nl = in_ * 8 + q * 2 - (ch & 1) * 32;
                        Cs[nl * 132 + mrow]           = acc[im][in_][0];
                        Cs[(nl + 1) * 132 + mrow]     = acc[im][in_][1];
                        Cs[nl * 132 + mrow + 8]       = acc[im][in_][2];
                        Cs[(nl + 1) * 132 + mrow + 8] = acc[im][in_][3];
                    }
                }
            }
            __syncthreads();
            for (int t = tid; t < 32 * 128; t += 256) {
                int nl = t >> 7, ml = t & 127;
                int n = n0 + ch * 32 + nl;
                int m = m0 + ml;
                int b = m >> 12, s = m & (SP - 1);
                size_t addr = (size_t)b * CHN * SP + (size_t)n * SP + s;
                Cout[addr] = Cs[nl * 132 + ml] + bias[n] + resid[addr];
            }
        }
    }
}

// ---------------- tensor-core attention (tf32), half2 output ----------------
#define AT_SMEM 55040

__global__ void __launch_bounds__(256, 2) attn_mma()
{
    extern __shared__ float sm[];
    float* Ks = sm;              // [80][84]
    float* Vs = sm + 6720;       // [80][88]

    int tid = threadIdx.x, lane = tid & 31, w = tid >> 5;
    int b = blockIdx.z, h = blockIdx.y;
    int q0 = blockIdx.x * 128;
    int mb = w * 16;
    int r = lane >> 2, q = lane & 3, q2 = q * 2;
    uint32_t sb = smem_u32(sm);

    const float* kg = g_k + (size_t)b * TT * INNER + h * HDIM;
    const float* vg = g_v + (size_t)b * TT * INNER + h * HDIM;

#pragma unroll
    for (int i = 0; i < 7; i++) {
        int cid = tid + i * 256;
        if (cid < 1540) {
            int row = cid / 20, ch = cid % 20;
            cp16(sb + (row * 84 + ch * 4) * 4, kg + (size_t)row * INNER + ch * 4, true);
            cp16(sb + (6720 + row * 88 + ch * 4) * 4, vg + (size_t)row * INNER + ch * 4, true);
        }
    }
    CP_COMMIT();

    const float* qg = g_q + ((size_t)b * SP + q0 + mb) * INNER + h * HDIM;
    float qf[10][4];
#pragma unroll
    for (int k8 = 0; k8 < 10; k8++) {
        int c = k8 * 8 + q;
        qf[k8][0] = qg[(size_t)r * INNER + c];
        qf[k8][1] = qg[(size_t)(r + 8) * INNER + c];
        qf[k8][2] = qg[(size_t)r * INNER + c + 4];
        qf[k8][3] = qg[(size_t)(r + 8) * INNER + c + 4];
    }

    if (tid < 240) {
        int row = 77 + tid / 80, col = tid % 80;
        Ks[row * 84 + col] = 0.f;
        Vs[row * 88 + col] = 0.f;
    }
    CP_WAIT0();
    __syncthreads();

    float acc[10][4];
#pragma unroll
    for (int i = 0; i < 10; i++)
#pragma unroll
        for (int j = 0; j < 4; j++) acc[i][j] = 0.f;

#pragma unroll
    for (int k8 = 0; k8 < 10; k8++) {
        int kr = k8 * 8 + q;
        unsigned a0 = __float_as_uint(qf[k8][0]);
        unsigned a1 = __float_as_uint(qf[k8][1]);
        unsigned a2 = __float_as_uint(qf[k8][2]);
        unsigned a3 = __float_as_uint(qf[k8][3]);
#pragma unroll
        for (int in_ = 0; in_ < 10; in_++) {
            int tcol = in_ * 8 + r;
            unsigned b0 = __float_as_uint(Ks[tcol * 84 + kr]);
            unsigned b1 = __float_as_uint(Ks[tcol * 84 + kr + 4]);
            mma_tf32(acc[in_], a0, a1, a2, a3, b0, b1);
        }
    }

    const float scale = 0.11180339887498949f;
    float invs[2];
#pragma unroll
    for (int hf = 0; hf < 2; hf++) {
        float mx = -1e30f;
#pragma unroll
        for (int in_ = 0; in_ < 10; in_++) {
            int c0 = in_ * 8 + q2;
            float v0 = (c0     < TT) ? acc[in_][hf * 2]     * scale : -1e30f;
            float v1 = (c0 + 1 < TT) ? acc[in_][hf * 2 + 1] * scale : -1e30f;
            acc[in_][hf * 2] = v0; acc[in_][hf * 2 + 1] = v1;
            mx = fmaxf(mx, fmaxf(v0, v1));
        }
        mx = fmaxf(mx, __shfl_xor_sync(0xffffffffu, mx, 1));
        mx = fmaxf(mx, __shfl_xor_sync(0xffffffffu, mx, 2));
        float s = 0.f;
#pragma unroll
        for (int in_ = 0; in_ < 10; in_++) {
            int c0 = in_ * 8 + q2;
            float e0 = (c0     < TT) ? __expf(acc[in_][hf * 2]     - mx) : 0.f;
            float e1 = (c0 + 1 < TT) ? __expf(acc[in_][hf * 2 + 1] - mx) : 0.f;
            acc[in_][hf * 2] = e0; acc[in_][hf * 2 + 1] = e1;
            s += e0 + e1;
        }
        s += __shfl_xor_sync(0xffffffffu, s, 1);
        s += __shfl_xor_sync(0xffffffffu, s, 2);
        invs[hf] = 1.f / s;
    }

    float oc[10][4];
#pragma unroll
    for (int i = 0; i < 10; i++)
#pragma unroll
        for (int j = 0; j < 4; j++) oc[i][j] = 0.f;

    int S0 = (r << 2) | (q >> 1);
    int S2 = S0 + 2;
    bool odd = (q & 1) != 0;
#pragma unroll
    for (int k8 = 0; k8 < 10; k8++) {
        float v0 = __shfl_sync(0xffffffffu, acc[k8][0], S0);
        float v1 = __shfl_sync(0xffffffffu, acc[k8][1], S0);
        float v2 = __shfl_sync(0xffffffffu, acc[k8][2], S0);
        float v3 = __shfl_sync(0xffffffffu, acc[k8][3], S0);
        float u0 = __shfl_sync(0xffffffffu, acc[k8][0], S2);
        float u1 = __shfl_sync(0xffffffffu, acc[k8][1], S2);
        float u2 = __shfl_sync(0xffffffffu, acc[k8][2], S2);
        float u3 = __shfl_sync(0xffffffffu, acc[k8][3], S2);
        unsigned a0 = __float_as_uint(odd ? v1 : v0);
        unsigned a1 = __float_as_uint(odd ? v3 : v2);
        unsigned a2 = __float_as_uint(odd ? u1 : u0);
        unsigned a3 = __float_as_uint(odd ? u3 : u2);
        int kr = k8 * 8 + q;
#pragma unroll
        for (int in_ = 0; in_ < 10; in_++) {
            int ncol = in_ * 8 + r;
            unsigned b0 = __float_as_uint(Vs[kr * 88 + ncol]);
            unsigned b1 = __float_as_uint(Vs[(kr + 4) * 88 + ncol]);
            mma_tf32(oc[in_], a0, a1, a2, a3, b0, b1);
        }
    }

    __half* og = g_at16 + ((size_t)b * SP + q0 + mb) * INNER + h * HDIM;
#pragma unroll
    for (int in_ = 0; in_ < 10; in_++) {
        int c = in_ * 8 + q2;
        *(__half2*)(og + (size_t)r * INNER + c) =
            __floats2half2_rn(oc[in_][0] * invs[0], oc[in_][1] * invs[0]);
        *(__half2*)(og + (size_t)(r + 8) * INNER + c) =
            __floats2half2_rn(oc[in_][2] * invs[1], oc[in_][3] * invs[1]);
    }
}

// ---------------- launch ----------------
extern "C" void kernel_launch(void* const* d_in, const int* in_sizes, int n_in,
                              void* d_out, int out_size)
{
    (void)in_sizes; (void)n_in; (void)out_size;
    const float* hs  = (const float*)d_in[0];
    const float* enc = (const float*)d_in[1];
    const float* lnw = (const float*)d_in[2];
    const float* lnb = (const float*)d_in[3];
    const float* wq  = (const float*)d_in[4];
    const float* wk  = (const float*)d_in[5];
    const float* wv  = (const float*)d_in[6];
    const float* wo  = (const float*)d_in[7];
    const float* bo  = (const float*)d_in[8];
    float* out = (float*)d_out;

    float *p_q, *p_k, *p_v;
    __half *p_x16, *p_at16, *p_e16, *p_wq16, *p_wk16, *p_wv16, *p_wo16;
    cudaGetSymbolAddress((void**)&p_q,    g_q);
    cudaGetSymbolAddress((void**)&p_k,    g_k);
    cudaGetSymbolAddress((void**)&p_v,    g_v);
    cudaGetSymbolAddress((void**)&p_x16,  g_x16);
    cudaGetSymbolAddress((void**)&p_at16, g_at16);
    cudaGetSymbolAddress((void**)&p_e16,  g_e16);
    cudaGetSymbolAddress((void**)&p_wq16, g_wq16);
    cudaGetSymbolAddress((void**)&p_wk16, g_wk16);
    cudaGetSymbolAddress((void**)&p_wv16, g_wv16);
    cudaGetSymbolAddress((void**)&p_wo16, g_wo16);

    cudaFuncSetAttribute(gemm_h<0, false>,
                         cudaFuncAttributeMaxDynamicSharedMemorySize, HGSMEM);
    cudaFuncSetAttribute(gemm_h<0, true>,
                         cudaFuncAttributeMaxDynamicSharedMemorySize, HGSMEM);
    cudaFuncSetAttribute(gemm_h<1, false>,
                         cudaFuncAttributeMaxDynamicSharedMemorySize, HGSMEM);
    cudaFuncSetAttribute(attn_mma,
                         cudaFuncAttributeMaxDynamicSharedMemorySize, AT_SMEM);

    // one-time fp16 conversions
    cvt_w_t<<<dim3(INNER / 32, CHN / 32), 256>>>(wq, p_wq16, CHN, INNER);
    cvt_w_t<<<dim3(INNER / 32, XDIM / 32), 256>>>(wk, p_wk16, XDIM, INNER);
    cvt_w_t<<<dim3(INNER / 32, XDIM / 32), 256>>>(wv, p_wv16, XDIM, INNER);
    cvt_w_t<<<dim3(CHN / 32, INNER / 32), 256>>>(wo, p_wo16, INNER, CHN);
    {
        int n = BATCH * TT * XDIM;
        cvt16<<<(n + 255) / 256, 256>>>(enc, p_e16, n);
    }

    // LN stats + normalize/transpose to fp16 [b][s][c]
    ln_stats<<<dim3(SP / 256, BATCH), 256>>>(hs);
    ln_t16<<<dim3(SP / 32, CHN / 32, BATCH), 256>>>(hs, lnw, lnb);

    // Q = x16 @ wq16^T (fp32 out)
    gemm_h<0, false><<<dim3(INNER / 128, (BATCH * SP) / 128), 256, HGSMEM>>>(
        p_x16, p_wq16, p_q, BATCH * SP, INNER, CHN, CHN, nullptr, nullptr);

    // K, V = e16 @ w^T   (M = 1232, guarded)
    int mkv = (BATCH * TT + 127) / 128;
    gemm_h<0, true><<<dim3(INNER / 128, mkv), 256, HGSMEM>>>(
        p_e16, p_wk16, p_k, BATCH * TT, INNER, XDIM, XDIM, nullptr, nullptr);
    gemm_h<0, true><<<dim3(INNER / 128, mkv), 256, HGSMEM>>>(
        p_e16, p_wv16, p_v, BATCH * TT, INNER, XDIM, XDIM, nullptr, nullptr);

    // attention (tf32 tensor-core)
    attn_mma<<<dim3(SP / 128, NHE, BATCH), 256, AT_SMEM>>>();

    // out = at16 @ wo16^T + bo + residual (transposed store, fp32)
    gemm_h<1, false><<<dim3(CHN / 128, (BATCH * SP) / 128), 256, HGSMEM>>>(
        p_at16, p_wo16, out, BATCH * SP, CHN, INNER, INNER, bo, hs);
}